// round 3
// baseline (speedup 1.0000x reference)
#include <cuda_runtime.h>

#define NB 2
#define NC 64
#define D  64
#define NVOX (D*D*D)            // 262144
#define NCH  (NB*NC)            // 128
#define TOT  (NCH*NVOX)         // 33554432

#define FIX_T   0.02f
#define MAXFIX  (1<<22)

// Scratch (no cudaMalloc allowed): proj output preserved for fixup + 2 temps
__device__ float2 g_p [TOT];    // (qk, qkv) bit-exact proj output
__device__ float2 g_t1[TOT];    // after w pass
__device__ float2 g_t2[TOT];    // after h pass
__device__ int    g_cnt;
__device__ int    g_fixlist[MAXFIX];

__global__ void reset_kernel() { g_cnt = 0; }

// ---------------------------------------------------------------------------
// Stage 1: q = Wq m, k = Wk f, v = Wv f per voxel, strict sequential FMA over
// c (ascending, single accumulator) to bit-match Eigen/XLA-CPU gemm rounding.
// qk = q*k; qkv = qk*v  (single roundings, ref order).
// ---------------------------------------------------------------------------
__global__ __launch_bounds__(256) void proj_kernel(
    const float* __restrict__ mov, const float* __restrict__ fix,
    const float* __restrict__ qw,  const float* __restrict__ kw,
    const float* __restrict__ vw)
{
    __shared__ float swq[NC*NC], swk[NC*NC], swv[NC*NC];
    const int tid = threadIdx.x;
    for (int i = tid; i < NC*NC; i += 256) {
        swq[i] = qw[i]; swk[i] = kw[i]; swv[i] = vw[i];
    }
    __syncthreads();

    const int gid = blockIdx.x * 256 + tid;     // 0 .. NB*NVOX-1
    const int b   = (gid >= NVOX) ? 1 : 0;
    const int n   = gid - b * NVOX;

    const float* mp = mov + (long)b*NC*NVOX + n;
    const float* fp = fix + (long)b*NC*NVOX + n;

    float m[NC], f[NC];
    #pragma unroll
    for (int c = 0; c < NC; c++) {
        m[c] = mp[(long)c*NVOX];
        f[c] = fp[(long)c*NVOX];
    }

    float2* op = g_p + (long)b*NC*NVOX + n;

    for (int l = 0; l < NC; l++) {
        const float4* wq4 = (const float4*)(swq + l*NC);
        const float4* wk4 = (const float4*)(swk + l*NC);
        const float4* wv4 = (const float4*)(swv + l*NC);
        float aq = 0.f, ak = 0.f, av = 0.f;
        #pragma unroll
        for (int c4 = 0; c4 < NC/4; c4++) {
            const float4 a  = wq4[c4];
            const float4 bb = wk4[c4];
            const float4 d  = wv4[c4];
            // strict sequential chains, ascending c, single accumulator each
            aq = __fmaf_rn(a.x,  m[4*c4+0], aq);
            aq = __fmaf_rn(a.y,  m[4*c4+1], aq);
            aq = __fmaf_rn(a.z,  m[4*c4+2], aq);
            aq = __fmaf_rn(a.w,  m[4*c4+3], aq);
            ak = __fmaf_rn(bb.x, f[4*c4+0], ak);
            ak = __fmaf_rn(bb.y, f[4*c4+1], ak);
            ak = __fmaf_rn(bb.z, f[4*c4+2], ak);
            ak = __fmaf_rn(bb.w, f[4*c4+3], ak);
            av = __fmaf_rn(d.x,  f[4*c4+0], av);
            av = __fmaf_rn(d.y,  f[4*c4+1], av);
            av = __fmaf_rn(d.z,  f[4*c4+2], av);
            av = __fmaf_rn(d.w,  f[4*c4+3], av);
        }
        const float qk  = __fmul_rn(aq, ak);
        const float qkv = __fmul_rn(qk, av);
        op[(long)l*NVOX] = make_float2(qk, qkv);
    }
}

// ---------------------------------------------------------------------------
// Stage 2a: fast box sum along W.  g_p -> g_t1
// ---------------------------------------------------------------------------
__global__ __launch_bounds__(256) void box_w_kernel()
{
    __shared__ float2 s[4][D];
    const int t = threadIdx.x;
    const int i = t & 63;
    const int r = t >> 6;
    const long base = ((long)blockIdx.x * 4 + r) * D;

    s[r][i] = g_p[base + i];
    __syncthreads();

    const int lo = (i - 4 < 0) ? 0 : i - 4;
    const int hi = (i + 4 > D-1) ? D-1 : i + 4;
    float sx = 0.f, sy = 0.f;
    for (int j = lo; j <= hi; j++) { sx += s[r][j].x; sy += s[r][j].y; }
    g_t1[base + i] = make_float2(sx, sy);
}

// ---------------------------------------------------------------------------
// Stage 2b: fast box sum along H (ring-buffer sliding window).  g_t1 -> g_t2
// ---------------------------------------------------------------------------
__global__ __launch_bounds__(256) void box_h_kernel()
{
    const int t    = threadIdx.x;
    const int w    = t & 63;
    const int z    = blockIdx.x * 4 + (t >> 6);
    const int chan = blockIdx.y;
    const long base = (long)chan*NVOX + (long)z*(D*D) + w;

    float2 ring[9];
    float sx = 0.f, sy = 0.f;
    #pragma unroll
    for (int j = 0; j < 4; j++) {
        float2 v = g_t1[base + (long)j*D];
        ring[j % 9] = v; sx += v.x; sy += v.y;
    }
    #pragma unroll
    for (int i = 0; i < D; i++) {
        const int j = i + 4;
        if (j < D) {
            float2 v = g_t1[base + (long)j*D];
            ring[j % 9] = v; sx += v.x; sy += v.y;
        }
        g_t2[base + (long)i*D] = make_float2(sx, sy);
        const int j2 = i - 4;
        if (j2 >= 0) { sx -= ring[j2 % 9].x; sy -= ring[j2 % 9].y; }
    }
}

// ---------------------------------------------------------------------------
// Stage 2c: fast box sum along Z + division; flag near-zero denominators.
// g_t2 -> out
// ---------------------------------------------------------------------------
__global__ __launch_bounds__(256) void box_z_div_kernel(float* __restrict__ out)
{
    const int t    = threadIdx.x;
    const int w    = t & 63;
    const int h    = blockIdx.x * 4 + (t >> 6);
    const int chan = blockIdx.y;
    const long base = (long)chan*NVOX + (long)h*D + w;

    float2 ring[9];
    float sx = 0.f, sy = 0.f;
    #pragma unroll
    for (int j = 0; j < 4; j++) {
        float2 v = g_t2[base + (long)j*(D*D)];
        ring[j % 9] = v; sx += v.x; sy += v.y;
    }
    #pragma unroll
    for (int i = 0; i < D; i++) {
        const int j = i + 4;
        if (j < D) {
            float2 v = g_t2[base + (long)j*(D*D)];
            ring[j % 9] = v; sx += v.x; sy += v.y;
        }
        const long oidx = base + (long)i*(D*D);
        out[oidx] = __fdiv_rn(sy, sx);
        if (fabsf(sx) < FIX_T) {
            int slot = atomicAdd(&g_cnt, 1);
            if (slot < MAXFIX) g_fixlist[slot] = (int)oidx;
        }
        const int j2 = i - 4;
        if (j2 >= 0) { sx -= ring[j2 % 9].x; sy -= ring[j2 % 9].y; }
    }
}

// ---------------------------------------------------------------------------
// Stage 3: exact fixup. For flagged voxels recompute both 9x9x9 sums by the
// reference's sequential in-bounds fold: window dims ascending (z,h,w),
// fp32 adds, init 0.  Reads bit-exact g_p.
// ---------------------------------------------------------------------------
__global__ __launch_bounds__(256) void fixup_kernel(float* __restrict__ out)
{
    int cnt = g_cnt; if (cnt > MAXFIX) cnt = MAXFIX;
    for (int idx = blockIdx.x*256 + threadIdx.x; idx < cnt; idx += gridDim.x*256) {
        const int v    = g_fixlist[idx];
        const int chan = v >> 18;              // / NVOX
        const int rem  = v & (NVOX-1);
        const int z = rem >> 12;
        const int h = (rem >> 6) & 63;
        const int w = rem & 63;
        const long cb = (long)chan*NVOX;

        const int zlo = z-4 < 0 ? 0 : z-4, zhi = z+4 > 63 ? 63 : z+4;
        const int hlo = h-4 < 0 ? 0 : h-4, hhi = h+4 > 63 ? 63 : h+4;
        const int wlo = w-4 < 0 ? 0 : w-4, whi = w+4 > 63 ? 63 : w+4;

        float sD = 0.f, sN = 0.f;
        for (int dz = zlo; dz <= zhi; dz++)
            for (int dh = hlo; dh <= hhi; dh++) {
                const float2* row = g_p + cb + ((long)dz*D + dh)*D;
                for (int dw = wlo; dw <= whi; dw++) {
                    float2 x = row[dw];
                    sD = __fadd_rn(sD, x.x);
                    sN = __fadd_rn(sN, x.y);
                }
            }
        out[v] = __fdiv_rn(sN, sD);
    }
}

extern "C" void kernel_launch(void* const* d_in, const int* in_sizes, int n_in,
                              void* d_out, int out_size) {
    (void)in_sizes; (void)n_in; (void)out_size;
    const float* mov = (const float*)d_in[0];
    const float* fix = (const float*)d_in[1];
    const float* qw  = (const float*)d_in[2];
    const float* kw  = (const float*)d_in[3];
    const float* vw  = (const float*)d_in[4];
    float* out = (float*)d_out;

    reset_kernel<<<1, 1>>>();
    proj_kernel<<<(NB*NVOX)/256, 256>>>(mov, fix, qw, kw, vw);
    box_w_kernel<<<TOT/256, 256>>>();
    box_h_kernel<<<dim3(16, NCH), 256>>>();
    box_z_div_kernel<<<dim3(16, NCH), 256>>>(out);
    fixup_kernel<<<512, 256>>>(out);
}

// round 4
// speedup vs baseline: 1.0248x; 1.0248x over previous
#include <cuda_runtime.h>

#define NB 2
#define NC 64
#define D  64
#define NVOX (D*D*D)            // 262144
#define NCH  (NB*NC)            // 128
#define TOT  (NCH*NVOX)         // 33554432

#define FIX_T   0.02f
#define MAXFIX  (1<<22)

// Scratch (no cudaMalloc allowed): proj output preserved for fixup + 2 temps
__device__ float2 g_p [TOT];    // (qk, qkv) bit-exact proj output
__device__ float2 g_t1[TOT];    // after w pass
__device__ float2 g_t2[TOT];    // after h pass
__device__ int    g_cnt;
__device__ int    g_fixlist[MAXFIX];

__global__ void reset_kernel() { g_cnt = 0; }

// ---------------------------------------------------------------------------
// Stage 1: q = Wq m, k = Wk f, v = Wv f per voxel. The q and k chains are
// packed into fma.rn.f32x2 (each lane is IEEE fp32 FMA -> bit-identical to
// the scalar sequential chain over ascending c). v chain stays scalar FFMA.
// qk = q*k; qkv = qk*v (single roundings). Bit-exactness here is load-bearing
// for the near-zero-denominator voxels (see fixup).
// ---------------------------------------------------------------------------
__global__ __launch_bounds__(256) void proj_kernel(
    const float* __restrict__ mov, const float* __restrict__ fix,
    const float* __restrict__ qw,  const float* __restrict__ kw,
    const float* __restrict__ vw)
{
    __shared__ float2 swqk[NC*NC];   // (wq, wk) interleaved, 32 KB
    __shared__ float  swv [NC*NC];   // 16 KB
    const int tid = threadIdx.x;
    for (int i = tid; i < NC*NC; i += 256) {
        swqk[i] = make_float2(qw[i], kw[i]);
        swv[i]  = vw[i];
    }
    __syncthreads();

    const int gid = blockIdx.x * 256 + tid;     // 0 .. NB*NVOX-1
    const int b   = (gid >= NVOX) ? 1 : 0;
    const int n   = gid - b * NVOX;

    const float* mp = mov + (long)b*NC*NVOX + n;
    const float* fp = fix + (long)b*NC*NVOX + n;

    unsigned long long mf[NC];   // packed (m[c], f[c])
    float f[NC];
    #pragma unroll
    for (int c = 0; c < NC; c++) {
        const float mv = mp[(long)c*NVOX];
        const float fv = fp[(long)c*NVOX];
        f[c] = fv;
        asm("mov.b64 %0, {%1,%2};" : "=l"(mf[c]) : "f"(mv), "f"(fv));
    }

    float2* op = g_p + (long)b*NC*NVOX + n;

    for (int l = 0; l < NC; l++) {
        const ulonglong2* wrow = (const ulonglong2*)(swqk + (l<<6));
        const float4*     vrow = (const float4*)(swv + (l<<6));
        unsigned long long aqk = 0ull;   // lanes: (aq, ak)
        float av = 0.f;
        #pragma unroll
        for (int j = 0; j < NC/4; j++) {
            const ulonglong2 wa = wrow[2*j];      // c = 4j, 4j+1
            const ulonglong2 wb = wrow[2*j+1];    // c = 4j+2, 4j+3
            const float4 wv4 = vrow[j];
            asm("fma.rn.f32x2 %0, %1, %2, %0;" : "+l"(aqk) : "l"(wa.x), "l"(mf[4*j+0]));
            av = __fmaf_rn(wv4.x, f[4*j+0], av);
            asm("fma.rn.f32x2 %0, %1, %2, %0;" : "+l"(aqk) : "l"(wa.y), "l"(mf[4*j+1]));
            av = __fmaf_rn(wv4.y, f[4*j+1], av);
            asm("fma.rn.f32x2 %0, %1, %2, %0;" : "+l"(aqk) : "l"(wb.x), "l"(mf[4*j+2]));
            av = __fmaf_rn(wv4.z, f[4*j+2], av);
            asm("fma.rn.f32x2 %0, %1, %2, %0;" : "+l"(aqk) : "l"(wb.y), "l"(mf[4*j+3]));
            av = __fmaf_rn(wv4.w, f[4*j+3], av);
        }
        float aq, ak;
        asm("mov.b64 {%0,%1}, %2;" : "=f"(aq), "=f"(ak) : "l"(aqk));
        const float qk  = __fmul_rn(aq, ak);
        const float qkv = __fmul_rn(qk, av);
        op[(long)l*NVOX] = make_float2(qk, qkv);
    }
}

// ---------------------------------------------------------------------------
// Stage 2a: fast box sum along W (float4 = 2 outputs per thread). g_p -> g_t1
// ---------------------------------------------------------------------------
__global__ __launch_bounds__(256) void box_w_kernel()
{
    __shared__ float2 s[8][D];
    const int t  = threadIdx.x;
    const int wp = t & 31;          // w-pair: covers w = 2wp, 2wp+1
    const int r  = t >> 5;          // row 0..7
    const long rowbase = ((long)blockIdx.x * 8 + r) * D;   // float2-element idx

    const float4 in = ((const float4*)g_p)[(rowbase >> 1) + wp];
    s[r][2*wp]   = make_float2(in.x, in.y);
    s[r][2*wp+1] = make_float2(in.z, in.w);
    __syncthreads();

    float4 o;
    {
        const int i = 2*wp;
        const int lo = (i-4 < 0) ? 0 : i-4;
        const int hi = (i+4 > D-1) ? D-1 : i+4;
        float sx = 0.f, sy = 0.f;
        for (int j = lo; j <= hi; j++) { sx += s[r][j].x; sy += s[r][j].y; }
        o.x = sx; o.y = sy;
    }
    {
        const int i = 2*wp+1;
        const int lo = (i-4 < 0) ? 0 : i-4;
        const int hi = (i+4 > D-1) ? D-1 : i+4;
        float sx = 0.f, sy = 0.f;
        for (int j = lo; j <= hi; j++) { sx += s[r][j].x; sy += s[r][j].y; }
        o.z = sx; o.w = sy;
    }
    ((float4*)g_t1)[(rowbase >> 1) + wp] = o;
}

// ---------------------------------------------------------------------------
// Stage 2b: fast box sum along H (float4 ring sliding window). g_t1 -> g_t2
// ---------------------------------------------------------------------------
__global__ __launch_bounds__(256) void box_h_kernel()
{
    const int t    = threadIdx.x;
    const int wp   = t & 31;
    const int z    = blockIdx.x * 8 + (t >> 5);   // gridDim.x = 8
    const int chan = blockIdx.y;
    // float4 element index (2 float2 per float4)
    const long base = ((long)chan*NVOX + (long)z*(D*D)) / 2 + wp;
    const float4* src = (const float4*)g_t1;
    float4*       dst = (float4*)g_t2;

    float4 ring[9];
    float4 s = make_float4(0.f, 0.f, 0.f, 0.f);
    #pragma unroll
    for (int j = 0; j < 4; j++) {
        float4 v = src[base + (long)j*(D/2)];
        ring[j % 9] = v;
        s.x += v.x; s.y += v.y; s.z += v.z; s.w += v.w;
    }
    #pragma unroll
    for (int i = 0; i < D; i++) {
        const int j = i + 4;
        if (j < D) {
            float4 v = src[base + (long)j*(D/2)];
            ring[j % 9] = v;
            s.x += v.x; s.y += v.y; s.z += v.z; s.w += v.w;
        }
        dst[base + (long)i*(D/2)] = s;
        const int j2 = i - 4;
        if (j2 >= 0) {
            float4 v = ring[j2 % 9];
            s.x -= v.x; s.y -= v.y; s.z -= v.z; s.w -= v.w;
        }
    }
}

// ---------------------------------------------------------------------------
// Stage 2c: fast box sum along Z + division; flag near-zero denominators.
// g_t2 -> out
// ---------------------------------------------------------------------------
__global__ __launch_bounds__(256) void box_z_div_kernel(float* __restrict__ out)
{
    const int t    = threadIdx.x;
    const int wp   = t & 31;
    const int h    = blockIdx.x * 8 + (t >> 5);   // gridDim.x = 8
    const int chan = blockIdx.y;
    const long ebase = (long)chan*NVOX + (long)h*D + 2*wp;  // element idx (w=2wp)
    const long base  = ebase >> 1;                          // float4 idx
    const float4* src = (const float4*)g_t2;
    float2*       o2  = (float2*)out;

    float4 ring[9];
    float4 s = make_float4(0.f, 0.f, 0.f, 0.f);
    #pragma unroll
    for (int j = 0; j < 4; j++) {
        float4 v = src[base + (long)j*(D*D/2)];
        ring[j % 9] = v;
        s.x += v.x; s.y += v.y; s.z += v.z; s.w += v.w;
    }
    #pragma unroll
    for (int i = 0; i < D; i++) {
        const int j = i + 4;
        if (j < D) {
            float4 v = src[base + (long)j*(D*D/2)];
            ring[j % 9] = v;
            s.x += v.x; s.y += v.y; s.z += v.z; s.w += v.w;
        }
        const long eidx = ebase + (long)i*(D*D);
        o2[eidx >> 1] = make_float2(__fdiv_rn(s.y, s.x), __fdiv_rn(s.w, s.z));
        if (fabsf(s.x) < FIX_T) {
            int slot = atomicAdd(&g_cnt, 1);
            if (slot < MAXFIX) g_fixlist[slot] = (int)eidx;
        }
        if (fabsf(s.z) < FIX_T) {
            int slot = atomicAdd(&g_cnt, 1);
            if (slot < MAXFIX) g_fixlist[slot] = (int)(eidx + 1);
        }
        const int j2 = i - 4;
        if (j2 >= 0) {
            float4 v = ring[j2 % 9];
            s.x -= v.x; s.y -= v.y; s.z -= v.z; s.w -= v.w;
        }
    }
}

// ---------------------------------------------------------------------------
// Stage 3: exact fixup. For flagged voxels recompute both 9x9x9 sums by the
// reference's sequential in-bounds fold (ascending z,h,w; fp32 adds; init 0)
// over the bit-exact g_p field.
// ---------------------------------------------------------------------------
__global__ __launch_bounds__(256) void fixup_kernel(float* __restrict__ out)
{
    int cnt = g_cnt; if (cnt > MAXFIX) cnt = MAXFIX;
    for (int idx = blockIdx.x*256 + threadIdx.x; idx < cnt; idx += gridDim.x*256) {
        const int v    = g_fixlist[idx];
        const int chan = v >> 18;
        const int rem  = v & (NVOX-1);
        const int z = rem >> 12;
        const int h = (rem >> 6) & 63;
        const int w = rem & 63;
        const long cb = (long)chan*NVOX;

        const int zlo = z-4 < 0 ? 0 : z-4, zhi = z+4 > 63 ? 63 : z+4;
        const int hlo = h-4 < 0 ? 0 : h-4, hhi = h+4 > 63 ? 63 : h+4;
        const int wlo = w-4 < 0 ? 0 : w-4, whi = w+4 > 63 ? 63 : w+4;

        float sD = 0.f, sN = 0.f;
        for (int dz = zlo; dz <= zhi; dz++)
            for (int dh = hlo; dh <= hhi; dh++) {
                const float2* row = g_p + cb + ((long)dz*D + dh)*D;
                for (int dw = wlo; dw <= whi; dw++) {
                    float2 x = row[dw];
                    sD = __fadd_rn(sD, x.x);
                    sN = __fadd_rn(sN, x.y);
                }
            }
        out[v] = __fdiv_rn(sN, sD);
    }
}

extern "C" void kernel_launch(void* const* d_in, const int* in_sizes, int n_in,
                              void* d_out, int out_size) {
    (void)in_sizes; (void)n_in; (void)out_size;
    const float* mov = (const float*)d_in[0];
    const float* fix = (const float*)d_in[1];
    const float* qw  = (const float*)d_in[2];
    const float* kw  = (const float*)d_in[3];
    const float* vw  = (const float*)d_in[4];
    float* out = (float*)d_out;

    reset_kernel<<<1, 1>>>();
    proj_kernel<<<(NB*NVOX)/256, 256>>>(mov, fix, qw, kw, vw);
    box_w_kernel<<<TOT/512, 256>>>();
    box_h_kernel<<<dim3(8, NCH), 256>>>();
    box_z_div_kernel<<<dim3(8, NCH), 256>>>(out);
    fixup_kernel<<<512, 256>>>(out);
}